// round 1
// baseline (speedup 1.0000x reference)
#include <cuda_runtime.h>
#include <cuda_bf16.h>
#include <cstdint>

// Problem constants
#define BATCH 4
#define SEQ   2048
#define CDIM  1024
#define NHEAD 16
#define HDIM  64
#define MROWS (BATCH*SEQ)          // 8192
#define QKVN  (3*CDIM)             // 3072

// Scratch (static device memory — allowed; no runtime allocation)
__device__ float g_qkv[(size_t)MROWS * QKVN];   // [B*T, 3C]
__device__ float g_y  [(size_t)MROWS * CDIM];   // [B*T, C]

// ---------------------------------------------------------------------------
// SGEMM with bias: C[M,N] = A[M,K] @ B[K,N] + bias[N]
// 128x128 block tile, BK=16, 256 threads, 8x8 per-thread microtile.
// M,N,K all multiples of 128/128/16 for this problem — no bounds checks.
// ---------------------------------------------------------------------------
__global__ __launch_bounds__(256) void sgemm_bias_kernel(
    const float* __restrict__ A, const float* __restrict__ B,
    const float* __restrict__ bias, float* __restrict__ Cmat,
    int M, int N, int K)
{
    __shared__ float As[16][128];
    __shared__ float Bs[16][128];

    const int tid  = threadIdx.x;
    const int brow = blockIdx.y * 128;
    const int bcol = blockIdx.x * 128;
    const int tr   = (tid >> 4) << 3;   // 0..120
    const int tc   = (tid & 15) << 3;   // 0..120

    float acc[8][8];
#pragma unroll
    for (int i = 0; i < 8; i++)
#pragma unroll
        for (int j = 0; j < 8; j++) acc[i][j] = 0.f;

    for (int k0 = 0; k0 < K; k0 += 16) {
        // Load A tile (128x16) transposed into As[k][m]; 512 float4 total.
#pragma unroll
        for (int l = 0; l < 2; l++) {
            int idx = tid + l * 256;            // 0..511
            int m   = idx >> 2;                 // 0..127
            int kk  = (idx & 3) << 2;           // 0,4,8,12
            float4 v = *(const float4*)&A[(size_t)(brow + m) * K + k0 + kk];
            As[kk + 0][m] = v.x;
            As[kk + 1][m] = v.y;
            As[kk + 2][m] = v.z;
            As[kk + 3][m] = v.w;
            // Load B tile (16x128) directly; 512 float4 total.
            int kb = idx >> 5;                  // 0..15
            int n4 = (idx & 31) << 2;           // 0..124
            *(float4*)&Bs[kb][n4] =
                *(const float4*)&B[(size_t)(k0 + kb) * N + bcol + n4];
        }
        __syncthreads();

#pragma unroll
        for (int kk = 0; kk < 16; kk++) {
            float a[8], bb[8];
#pragma unroll
            for (int i = 0; i < 8; i++) a[i]  = As[kk][tr + i];
#pragma unroll
            for (int j = 0; j < 8; j++) bb[j] = Bs[kk][tc + j];
#pragma unroll
            for (int i = 0; i < 8; i++)
#pragma unroll
                for (int j = 0; j < 8; j++)
                    acc[i][j] += a[i] * bb[j];
        }
        __syncthreads();
    }

#pragma unroll
    for (int i = 0; i < 8; i++)
#pragma unroll
        for (int j = 0; j < 8; j++)
            Cmat[(size_t)(brow + tr + i) * N + bcol + tc + j] =
                acc[i][j] + bias[bcol + tc + j];
}

// ---------------------------------------------------------------------------
// Causal flash attention, fp32, online softmax.
// Grid: (T/64, H, B). Block: 256 threads as 16x16.
// BQ=64 queries, BKV=32 keys/values per inner tile, hd=64.
// Each thread: 4 query rows (ty*4+i), S-cols tx*2+j, O-cols tx*4+j.
// Reads q/k/v in-place from g_qkv [B*T, 3C] (q at +0, k at +C, v at +2C).
// Writes y [B*T, C].
// ---------------------------------------------------------------------------
__global__ __launch_bounds__(256) void attn_kernel(
    const float* __restrict__ qkv, float* __restrict__ y)
{
    const int qb = blockIdx.x;   // query tile 0..31
    const int h  = blockIdx.y;   // head 0..15
    const int b  = blockIdx.z;   // batch 0..3
    const int tid = threadIdx.x;
    const int ty = tid >> 4;     // 0..15
    const int tx = tid & 15;     // 0..15

    __shared__ float Qs[64][HDIM + 1];
    __shared__ float Ks[32][HDIM + 1];
    __shared__ float Vs[32][HDIM + 1];
    __shared__ float Ps[64][33];

    const float* base = qkv + (size_t)(b * SEQ) * QKVN + h * HDIM;

    // Load Q tile: 64x64 floats = 1024 float4, 4 per thread.
#pragma unroll
    for (int l = 0; l < 4; l++) {
        int idx = tid + l * 256;
        int r   = idx >> 4;              // 0..63
        int c4  = (idx & 15) << 2;       // 0..60
        float4 v = *(const float4*)&base[(size_t)(qb * 64 + r) * QKVN + c4];
        Qs[r][c4 + 0] = v.x; Qs[r][c4 + 1] = v.y;
        Qs[r][c4 + 2] = v.z; Qs[r][c4 + 3] = v.w;
    }

    float mrow[4], lrow[4], acc[4][4];
#pragma unroll
    for (int i = 0; i < 4; i++) {
        mrow[i] = -1e30f;
        lrow[i] = 0.f;
#pragma unroll
        for (int j = 0; j < 4; j++) acc[i][j] = 0.f;
    }

    const int n_tiles = 2 * qb + 2;   // causal: kv tiles of 32 covering [0, qb*64+63]
    const int q0 = qb * 64;

    for (int kt = 0; kt < n_tiles; kt++) {
        __syncthreads();  // guard Ks/Vs (and Qs on first iter) against prior reads

        // Load K and V tiles: 32x64 each = 512 float4 each, 2 per thread each.
#pragma unroll
        for (int l = 0; l < 2; l++) {
            int idx = tid + l * 256;
            int r   = idx >> 4;              // 0..31
            int c4  = (idx & 15) << 2;       // 0..60
            size_t row_off = (size_t)(kt * 32 + r) * QKVN + c4;
            float4 kv = *(const float4*)&base[CDIM + row_off];
            Ks[r][c4 + 0] = kv.x; Ks[r][c4 + 1] = kv.y;
            Ks[r][c4 + 2] = kv.z; Ks[r][c4 + 3] = kv.w;
            float4 vv = *(const float4*)&base[2 * CDIM + row_off];
            Vs[r][c4 + 0] = vv.x; Vs[r][c4 + 1] = vv.y;
            Vs[r][c4 + 2] = vv.z; Vs[r][c4 + 3] = vv.w;
        }
        __syncthreads();

        // S = Q K^T for my 4x2 sub-tile
        float s[4][2];
#pragma unroll
        for (int i = 0; i < 4; i++) { s[i][0] = 0.f; s[i][1] = 0.f; }
#pragma unroll
        for (int d = 0; d < HDIM; d++) {
            float a0 = Qs[ty * 4 + 0][d];
            float a1 = Qs[ty * 4 + 1][d];
            float a2 = Qs[ty * 4 + 2][d];
            float a3 = Qs[ty * 4 + 3][d];
            float b0 = Ks[tx * 2 + 0][d];
            float b1 = Ks[tx * 2 + 1][d];
            s[0][0] += a0 * b0; s[0][1] += a0 * b1;
            s[1][0] += a1 * b0; s[1][1] += a1 * b1;
            s[2][0] += a2 * b0; s[2][1] += a2 * b1;
            s[3][0] += a3 * b0; s[3][1] += a3 * b1;
        }

        // Scale + causal mask
        const int k0 = kt * 32;
#pragma unroll
        for (int i = 0; i < 4; i++) {
#pragma unroll
            for (int j = 0; j < 2; j++) {
                float sv = s[i][j] * 0.125f;   // 1/sqrt(64)
                if (k0 + tx * 2 + j > q0 + ty * 4 + i) sv = -1e30f;
                s[i][j] = sv;
            }
        }

        // Online softmax update (row reduce across the 16-lane tx group)
#pragma unroll
        for (int i = 0; i < 4; i++) {
            float lm = fmaxf(s[i][0], s[i][1]);
#pragma unroll
            for (int off = 1; off < 16; off <<= 1)
                lm = fmaxf(lm, __shfl_xor_sync(0xffffffffu, lm, off));
            float mnew  = fmaxf(mrow[i], lm);
            float alpha = __expf(mrow[i] - mnew);
            float p0 = __expf(s[i][0] - mnew);
            float p1 = __expf(s[i][1] - mnew);
            float ls = p0 + p1;
#pragma unroll
            for (int off = 1; off < 16; off <<= 1)
                ls += __shfl_xor_sync(0xffffffffu, ls, off);
            lrow[i] = lrow[i] * alpha + ls;
            mrow[i] = mnew;
#pragma unroll
            for (int j = 0; j < 4; j++) acc[i][j] *= alpha;
            Ps[ty * 4 + i][tx * 2 + 0] = p0;
            Ps[ty * 4 + i][tx * 2 + 1] = p1;
        }
        __syncthreads();

        // O += P @ V
#pragma unroll
        for (int c = 0; c < 32; c++) {
            float p0 = Ps[ty * 4 + 0][c];
            float p1 = Ps[ty * 4 + 1][c];
            float p2 = Ps[ty * 4 + 2][c];
            float p3 = Ps[ty * 4 + 3][c];
            float v0 = Vs[c][tx * 4 + 0];
            float v1 = Vs[c][tx * 4 + 1];
            float v2 = Vs[c][tx * 4 + 2];
            float v3 = Vs[c][tx * 4 + 3];
            acc[0][0] += p0 * v0; acc[0][1] += p0 * v1; acc[0][2] += p0 * v2; acc[0][3] += p0 * v3;
            acc[1][0] += p1 * v0; acc[1][1] += p1 * v1; acc[1][2] += p1 * v2; acc[1][3] += p1 * v3;
            acc[2][0] += p2 * v0; acc[2][1] += p2 * v1; acc[2][2] += p2 * v2; acc[2][3] += p2 * v3;
            acc[3][0] += p3 * v0; acc[3][1] += p3 * v1; acc[3][2] += p3 * v2; acc[3][3] += p3 * v3;
        }
    }

    // Normalize and write y[B*T, C] at column h*64
#pragma unroll
    for (int i = 0; i < 4; i++) {
        float inv_l = 1.0f / lrow[i];
        int r = ty * 4 + i;
#pragma unroll
        for (int j = 0; j < 4; j++) {
            int dc = tx * 4 + j;
            y[(size_t)(b * SEQ + qb * 64 + r) * CDIM + h * HDIM + dc] =
                acc[i][j] * inv_l;
        }
    }
}

// ---------------------------------------------------------------------------
// Launch
// ---------------------------------------------------------------------------
extern "C" void kernel_launch(void* const* d_in, const int* in_sizes, int n_in,
                              void* d_out, int out_size)
{
    const float* x      = (const float*)d_in[0];
    const float* W_attn = (const float*)d_in[1];
    const float* b_attn = (const float*)d_in[2];
    const float* W_proj = (const float*)d_in[3];
    const float* b_proj = (const float*)d_in[4];
    float* out = (float*)d_out;

    float* qkv = nullptr;
    float* ybuf = nullptr;
    cudaGetSymbolAddress((void**)&qkv, g_qkv);
    cudaGetSymbolAddress((void**)&ybuf, g_y);

    // 1) QKV projection: [8192,1024] @ [1024,3072] + bias
    {
        dim3 grid(QKVN / 128, MROWS / 128);
        sgemm_bias_kernel<<<grid, 256>>>(x, W_attn, b_attn, qkv,
                                         MROWS, QKVN, CDIM);
    }
    // 2) Causal attention
    {
        dim3 grid(SEQ / 64, NHEAD, BATCH);
        attn_kernel<<<grid, 256>>>(qkv, ybuf);
    }
    // 3) Output projection: [8192,1024] @ [1024,1024] + bias -> d_out
    {
        dim3 grid(CDIM / 128, MROWS / 128);
        sgemm_bias_kernel<<<grid, 256>>>(ybuf, W_proj, b_proj, out,
                                         MROWS, CDIM, CDIM);
    }
}

// round 2
// speedup vs baseline: 3.4695x; 3.4695x over previous
#include <cuda_runtime.h>
#include <cuda_bf16.h>
#include <cstdint>

// Problem constants
#define BATCH 4
#define SEQ   2048
#define CDIM  1024
#define NHEAD 16
#define HDIM  64
#define MROWS (BATCH*SEQ)          // 8192
#define QKVN  (3*CDIM)             // 3072

// Scratch
__device__ float g_qkv[(size_t)MROWS * QKVN];   // [B*T, 3C]
__device__ float g_y  [(size_t)MROWS * CDIM];   // [B*T, C]

__device__ __forceinline__ float to_tf32(float x) {
    asm("cvt.rna.tf32.f32 %0, %0;" : "+f"(x));
    return x;
}

__device__ __forceinline__ void mma_tf32(
    float& c0, float& c1, float& c2, float& c3,
    uint32_t a0, uint32_t a1, uint32_t a2, uint32_t a3,
    uint32_t b0, uint32_t b1)
{
    asm volatile(
        "mma.sync.aligned.m16n8k8.row.col.f32.tf32.tf32.f32 "
        "{%0,%1,%2,%3}, {%4,%5,%6,%7}, {%8,%9}, {%0,%1,%2,%3};"
        : "+f"(c0), "+f"(c1), "+f"(c2), "+f"(c3)
        : "r"(a0), "r"(a1), "r"(a2), "r"(a3), "r"(b0), "r"(b1));
}

// ---------------------------------------------------------------------------
// TF32 tensor-core GEMM with bias: C[M,N] = A[M,K] @ B[K,N] + bias[N]
// 128x128 block, BK=32, 256 threads (8 warps, 2x4), warp tile 64x32.
// ---------------------------------------------------------------------------
#define ASTRIDE 36
#define BSTRIDE 136
__global__ __launch_bounds__(256) void gemm_tf32_bias(
    const float* __restrict__ A, const float* __restrict__ B,
    const float* __restrict__ bias, float* __restrict__ Cmat,
    int M, int N, int K)
{
    __shared__ float As[128 * ASTRIDE];   // [m][k], stride 36
    __shared__ float Bs[32 * BSTRIDE];    // [k][n], stride 136

    const int tid  = threadIdx.x;
    const int brow = blockIdx.y * 128;
    const int bcol = blockIdx.x * 128;
    const int w    = tid >> 5;
    const int lane = tid & 31;
    const int g    = lane >> 2;
    const int tig  = lane & 3;
    const int wr   = (w >> 2) * 64;    // warp m base (0 or 64)
    const int wc   = (w & 3) * 32;     // warp n base (0..96)

    float acc[4][4][4];                 // [mtile][ntile][frag]
#pragma unroll
    for (int i = 0; i < 4; i++)
#pragma unroll
        for (int j = 0; j < 4; j++)
#pragma unroll
            for (int f = 0; f < 4; f++) acc[i][j][f] = 0.f;

    for (int k0 = 0; k0 < K; k0 += 32) {
        __syncthreads();
        // A tile 128x32: 1024 float4, 4/thread
#pragma unroll
        for (int l = 0; l < 4; l++) {
            int idx = tid + l * 256;
            int m   = idx >> 3;
            int kk  = (idx & 7) << 2;
            float4 v = *(const float4*)&A[(size_t)(brow + m) * K + k0 + kk];
            v.x = to_tf32(v.x); v.y = to_tf32(v.y);
            v.z = to_tf32(v.z); v.w = to_tf32(v.w);
            *(float4*)&As[m * ASTRIDE + kk] = v;
            // B tile 32x128
            int kb = idx >> 5;
            int n4 = (idx & 31) << 2;
            float4 u = *(const float4*)&B[(size_t)(k0 + kb) * N + bcol + n4];
            u.x = to_tf32(u.x); u.y = to_tf32(u.y);
            u.z = to_tf32(u.z); u.w = to_tf32(u.w);
            *(float4*)&Bs[kb * BSTRIDE + n4] = u;
        }
        __syncthreads();

#pragma unroll
        for (int ks = 0; ks < 32; ks += 8) {
            uint32_t af[4][4], bf[4][2];
#pragma unroll
            for (int i = 0; i < 4; i++) {
                int r0 = wr + i * 16 + g;
                af[i][0] = __float_as_uint(As[r0 * ASTRIDE + ks + tig]);
                af[i][1] = __float_as_uint(As[(r0 + 8) * ASTRIDE + ks + tig]);
                af[i][2] = __float_as_uint(As[r0 * ASTRIDE + ks + tig + 4]);
                af[i][3] = __float_as_uint(As[(r0 + 8) * ASTRIDE + ks + tig + 4]);
            }
#pragma unroll
            for (int j = 0; j < 4; j++) {
                int c0 = wc + j * 8 + g;
                bf[j][0] = __float_as_uint(Bs[(ks + tig) * BSTRIDE + c0]);
                bf[j][1] = __float_as_uint(Bs[(ks + tig + 4) * BSTRIDE + c0]);
            }
#pragma unroll
            for (int i = 0; i < 4; i++)
#pragma unroll
                for (int j = 0; j < 4; j++)
                    mma_tf32(acc[i][j][0], acc[i][j][1], acc[i][j][2], acc[i][j][3],
                             af[i][0], af[i][1], af[i][2], af[i][3],
                             bf[j][0], bf[j][1]);
        }
    }

    // Epilogue
#pragma unroll
    for (int i = 0; i < 4; i++) {
#pragma unroll
        for (int j = 0; j < 4; j++) {
            int row = brow + wr + i * 16 + g;
            int col = bcol + wc + j * 8 + 2 * tig;
            float b0 = bias[col], b1 = bias[col + 1];
            float2 v0 = make_float2(acc[i][j][0] + b0, acc[i][j][1] + b1);
            float2 v1 = make_float2(acc[i][j][2] + b0, acc[i][j][3] + b1);
            *(float2*)&Cmat[(size_t)row * N + col] = v0;
            *(float2*)&Cmat[(size_t)(row + 8) * N + col] = v1;
        }
    }
}

// ---------------------------------------------------------------------------
// Causal flash attention with TF32 mma. Grid (T/64, H, B), 128 threads (4 warps).
// BQ=64 (warp: 16 rows), BKV=32, hd=64.
// ---------------------------------------------------------------------------
#define QSTR 68
#define KSTR 68
#define VSTR 72
#define PSTR 36
__global__ __launch_bounds__(128) void attn_tf32_kernel(
    const float* __restrict__ qkv, float* __restrict__ y)
{
    __shared__ float Qs[64 * QSTR];
    __shared__ float Ks[32 * KSTR];
    __shared__ float Vs[32 * VSTR];
    __shared__ float Ps[64 * PSTR];

    const int qb = blockIdx.x;
    const int h  = blockIdx.y;
    const int b  = blockIdx.z;
    const int tid = threadIdx.x;
    const int w    = tid >> 5;
    const int lane = tid & 31;
    const int g    = lane >> 2;
    const int tig  = lane & 3;
    const int mrow = w * 16 + g;   // my fragment row (and +8)

    const float* base = qkv + (size_t)(b * SEQ) * QKVN + h * HDIM;
    const int q0 = qb * 64;

    // Load Q tile 64x64 (tf32), 8 float4/thread
#pragma unroll
    for (int l = 0; l < 8; l++) {
        int idx = tid + l * 128;
        int r   = idx >> 4;
        int c4  = (idx & 15) << 2;
        float4 v = *(const float4*)&base[(size_t)(q0 + r) * QKVN + c4];
        v.x = to_tf32(v.x); v.y = to_tf32(v.y);
        v.z = to_tf32(v.z); v.w = to_tf32(v.w);
        *(float4*)&Qs[r * QSTR + c4] = v;
    }

    float o[8][4];
#pragma unroll
    for (int j = 0; j < 8; j++)
#pragma unroll
        for (int f = 0; f < 4; f++) o[j][f] = 0.f;
    float m0 = -1e30f, m1 = -1e30f, l0 = 0.f, l1 = 0.f;

    const int n_tiles = 2 * qb + 2;

    for (int kt = 0; kt < n_tiles; kt++) {
        __syncthreads();
        // K, V tiles 32x64 each: 4 float4/thread each
#pragma unroll
        for (int l = 0; l < 4; l++) {
            int idx = tid + l * 128;
            int r   = idx >> 4;
            int c4  = (idx & 15) << 2;
            size_t ro = (size_t)(kt * 32 + r) * QKVN + c4;
            float4 kv = *(const float4*)&base[CDIM + ro];
            kv.x = to_tf32(kv.x); kv.y = to_tf32(kv.y);
            kv.z = to_tf32(kv.z); kv.w = to_tf32(kv.w);
            *(float4*)&Ks[r * KSTR + c4] = kv;
            float4 vv = *(const float4*)&base[2 * CDIM + ro];
            vv.x = to_tf32(vv.x); vv.y = to_tf32(vv.y);
            vv.z = to_tf32(vv.z); vv.w = to_tf32(vv.w);
            *(float4*)&Vs[r * VSTR + c4] = vv;
        }
        __syncthreads();

        // S = Q K^T : warp rows [w*16, w*16+16), cols [0,32)
        float s[4][4];
#pragma unroll
        for (int j = 0; j < 4; j++)
#pragma unroll
            for (int f = 0; f < 4; f++) s[j][f] = 0.f;
#pragma unroll
        for (int ks = 0; ks < 64; ks += 8) {
            uint32_t a0 = __float_as_uint(Qs[mrow * QSTR + ks + tig]);
            uint32_t a1 = __float_as_uint(Qs[(mrow + 8) * QSTR + ks + tig]);
            uint32_t a2 = __float_as_uint(Qs[mrow * QSTR + ks + tig + 4]);
            uint32_t a3 = __float_as_uint(Qs[(mrow + 8) * QSTR + ks + tig + 4]);
#pragma unroll
            for (int j = 0; j < 4; j++) {
                int c0 = j * 8 + g;
                uint32_t b0 = __float_as_uint(Ks[c0 * KSTR + ks + tig]);
                uint32_t b1 = __float_as_uint(Ks[c0 * KSTR + ks + tig + 4]);
                mma_tf32(s[j][0], s[j][1], s[j][2], s[j][3], a0, a1, a2, a3, b0, b1);
            }
        }

        // scale + causal mask (only the 2 diagonal-straddling tiles need it)
        const int k0c = kt * 32;
        if (kt >= 2 * qb) {
#pragma unroll
            for (int j = 0; j < 4; j++) {
                int c = k0c + j * 8 + 2 * tig;
                int r0g = q0 + mrow, r1g = r0g + 8;
                s[j][0] = (c     <= r0g) ? s[j][0] * 0.125f : -1e30f;
                s[j][1] = (c + 1 <= r0g) ? s[j][1] * 0.125f : -1e30f;
                s[j][2] = (c     <= r1g) ? s[j][2] * 0.125f : -1e30f;
                s[j][3] = (c + 1 <= r1g) ? s[j][3] * 0.125f : -1e30f;
            }
        } else {
#pragma unroll
            for (int j = 0; j < 4; j++)
#pragma unroll
                for (int f = 0; f < 4; f++) s[j][f] *= 0.125f;
        }

        // Online softmax (rows mrow, mrow+8); reduce over 4 lanes sharing g
        float rm0 = -1e30f, rm1 = -1e30f;
#pragma unroll
        for (int j = 0; j < 4; j++) {
            rm0 = fmaxf(rm0, fmaxf(s[j][0], s[j][1]));
            rm1 = fmaxf(rm1, fmaxf(s[j][2], s[j][3]));
        }
#pragma unroll
        for (int off = 1; off < 4; off <<= 1) {
            rm0 = fmaxf(rm0, __shfl_xor_sync(0xffffffffu, rm0, off));
            rm1 = fmaxf(rm1, __shfl_xor_sync(0xffffffffu, rm1, off));
        }
        float mn0 = fmaxf(m0, rm0), mn1 = fmaxf(m1, rm1);
        float al0 = __expf(m0 - mn0), al1 = __expf(m1 - mn1);
        float ls0 = 0.f, ls1 = 0.f;
#pragma unroll
        for (int j = 0; j < 4; j++) {
            float p0 = __expf(s[j][0] - mn0);
            float p1 = __expf(s[j][1] - mn0);
            float p2 = __expf(s[j][2] - mn1);
            float p3 = __expf(s[j][3] - mn1);
            ls0 += p0 + p1; ls1 += p2 + p3;
            int c = j * 8 + 2 * tig;
            Ps[mrow * PSTR + c]           = to_tf32(p0);
            Ps[mrow * PSTR + c + 1]       = to_tf32(p1);
            Ps[(mrow + 8) * PSTR + c]     = to_tf32(p2);
            Ps[(mrow + 8) * PSTR + c + 1] = to_tf32(p3);
        }
#pragma unroll
        for (int off = 1; off < 4; off <<= 1) {
            ls0 += __shfl_xor_sync(0xffffffffu, ls0, off);
            ls1 += __shfl_xor_sync(0xffffffffu, ls1, off);
        }
        l0 = l0 * al0 + ls0;
        l1 = l1 * al1 + ls1;
        m0 = mn0; m1 = mn1;
#pragma unroll
        for (int j = 0; j < 8; j++) {
            o[j][0] *= al0; o[j][1] *= al0;
            o[j][2] *= al1; o[j][3] *= al1;
        }
        __syncwarp();

        // O += P @ V  (kv = 32 -> 4 ksteps; d = 64 -> 8 ntiles)
#pragma unroll
        for (int ks = 0; ks < 32; ks += 8) {
            uint32_t a0 = __float_as_uint(Ps[mrow * PSTR + ks + tig]);
            uint32_t a1 = __float_as_uint(Ps[(mrow + 8) * PSTR + ks + tig]);
            uint32_t a2 = __float_as_uint(Ps[mrow * PSTR + ks + tig + 4]);
            uint32_t a3 = __float_as_uint(Ps[(mrow + 8) * PSTR + ks + tig + 4]);
#pragma unroll
            for (int j = 0; j < 8; j++) {
                int c0 = j * 8 + g;
                uint32_t b0 = __float_as_uint(Vs[(ks + tig) * VSTR + c0]);
                uint32_t b1 = __float_as_uint(Vs[(ks + tig + 4) * VSTR + c0]);
                mma_tf32(o[j][0], o[j][1], o[j][2], o[j][3], a0, a1, a2, a3, b0, b1);
            }
        }
    }

    // Normalize & write y[B*T, C] at columns h*64 + ...
    float il0 = 1.0f / l0, il1 = 1.0f / l1;
    size_t r0 = (size_t)(b * SEQ + q0 + mrow) * CDIM + h * HDIM;
    size_t r1 = (size_t)(b * SEQ + q0 + mrow + 8) * CDIM + h * HDIM;
#pragma unroll
    for (int j = 0; j < 8; j++) {
        int c = j * 8 + 2 * tig;
        *(float2*)&y[r0 + c] = make_float2(o[j][0] * il0, o[j][1] * il0);
        *(float2*)&y[r1 + c] = make_float2(o[j][2] * il1, o[j][3] * il1);
    }
}

// ---------------------------------------------------------------------------
extern "C" void kernel_launch(void* const* d_in, const int* in_sizes, int n_in,
                              void* d_out, int out_size)
{
    const float* x      = (const float*)d_in[0];
    const float* W_attn = (const float*)d_in[1];
    const float* b_attn = (const float*)d_in[2];
    const float* W_proj = (const float*)d_in[3];
    const float* b_proj = (const float*)d_in[4];
    float* out = (float*)d_out;

    float* qkv = nullptr;
    float* ybuf = nullptr;
    cudaGetSymbolAddress((void**)&qkv, g_qkv);
    cudaGetSymbolAddress((void**)&ybuf, g_y);

    {   // QKV projection
        dim3 grid(QKVN / 128, MROWS / 128);
        gemm_tf32_bias<<<grid, 256>>>(x, W_attn, b_attn, qkv, MROWS, QKVN, CDIM);
    }
    {   // Attention
        dim3 grid(SEQ / 64, NHEAD, BATCH);
        attn_tf32_kernel<<<grid, 128>>>(qkv, ybuf);
    }
    {   // Output projection
        dim3 grid(CDIM / 128, MROWS / 128);
        gemm_tf32_bias<<<grid, 256>>>(ybuf, W_proj, b_proj, out, MROWS, CDIM, CDIM);
    }
}

// round 3
// speedup vs baseline: 7.3976x; 2.1321x over previous
#include <cuda_runtime.h>
#include <cuda_fp16.h>
#include <cstdint>

// Problem constants
#define BATCH 4
#define SEQ   2048
#define CDIM  1024
#define NHEAD 16
#define HDIM  64
#define MROWS (BATCH*SEQ)          // 8192
#define QKVN  (3*CDIM)             // 3072

// fp16 scratch
__device__ __half g_xh  [(size_t)MROWS * CDIM];
__device__ __half g_wah [(size_t)CDIM * QKVN];
__device__ __half g_wph [(size_t)CDIM * CDIM];
__device__ __half g_qkvh[(size_t)MROWS * QKVN];
__device__ __half g_yh  [(size_t)MROWS * CDIM];

// ---------------------------------------------------------------------------
__device__ __forceinline__ uint32_t smem_u32(const void* p) {
    uint32_t a;
    asm("{ .reg .u64 t; cvta.to.shared.u64 t, %1; cvt.u32.u64 %0, t; }" : "=r"(a) : "l"(p));
    return a;
}
__device__ __forceinline__ void cp16(uint32_t s, const void* g) {
    asm volatile("cp.async.cg.shared.global [%0], [%1], 16;" :: "r"(s), "l"(g));
}
#define CP_COMMIT() asm volatile("cp.async.commit_group;")
#define CP_WAIT(n)  asm volatile("cp.async.wait_group %0;" :: "n"(n))

#define LDSM_X4(r0,r1,r2,r3,addr) \
    asm volatile("ldmatrix.sync.aligned.m8n8.x4.shared.b16 {%0,%1,%2,%3},[%4];" \
        : "=r"(r0),"=r"(r1),"=r"(r2),"=r"(r3) : "r"(addr))
#define LDSM_X4_T(r0,r1,r2,r3,addr) \
    asm volatile("ldmatrix.sync.aligned.m8n8.x4.trans.shared.b16 {%0,%1,%2,%3},[%4];" \
        : "=r"(r0),"=r"(r1),"=r"(r2),"=r"(r3) : "r"(addr))

__device__ __forceinline__ void mma_f16(
    float& c0, float& c1, float& c2, float& c3,
    uint32_t a0, uint32_t a1, uint32_t a2, uint32_t a3,
    uint32_t b0, uint32_t b1)
{
    asm volatile(
        "mma.sync.aligned.m16n8k16.row.col.f32.f16.f16.f32 "
        "{%0,%1,%2,%3}, {%4,%5,%6,%7}, {%8,%9}, {%0,%1,%2,%3};"
        : "+f"(c0), "+f"(c1), "+f"(c2), "+f"(c3)
        : "r"(a0), "r"(a1), "r"(a2), "r"(a3), "r"(b0), "r"(b1));
}
__device__ __forceinline__ uint32_t pack_h2(float a, float b) {
    __half2 h = __floats2half2_rn(a, b);
    return *(uint32_t*)&h;
}

// ---------------------------------------------------------------------------
// fp32 -> fp16 convert (n divisible by 4)
// ---------------------------------------------------------------------------
__global__ void f2h_kernel(const float4* __restrict__ in, uint2* __restrict__ out, int n4) {
    int i = blockIdx.x * 256 + threadIdx.x;
    if (i < n4) {
        float4 v = in[i];
        out[i] = make_uint2(pack_h2(v.x, v.y), pack_h2(v.z, v.w));
    }
}

// ---------------------------------------------------------------------------
// fp16 tensor-core GEMM + bias: C[M,N] = A[M,K] @ B[K,N] + bias[N]
// 128x128 block, BK=32, 256 threads (8 warps 2x4), warp tile 64x32.
// Double-buffered smem via cp.async; ldmatrix operand fetch.
// ---------------------------------------------------------------------------
#define ASTR 40    // halves per A row (32 + 8 pad)
#define BSTR 136   // halves per B row (128 + 8 pad)
#define ASZ  (128*ASTR)
#define BSZ  (32*BSTR)

template<int WRITE_HALF>
__global__ __launch_bounds__(256) void hgemm_bias(
    const __half* __restrict__ A, const __half* __restrict__ B,
    const float* __restrict__ bias, void* __restrict__ Cout,
    int M, int N, int K)
{
    __shared__ __align__(16) __half As[2 * ASZ];
    __shared__ __align__(16) __half Bs[2 * BSZ];

    const int tid  = threadIdx.x;
    const int brow = blockIdx.y * 128;
    const int bcol = blockIdx.x * 128;
    const int w    = tid >> 5;
    const int lane = tid & 31;
    const int g    = lane >> 2;
    const int tig  = lane & 3;
    const int wr   = (w >> 2) * 64;
    const int wc   = (w & 3) * 32;

    const uint32_t as_u = smem_u32(As);
    const uint32_t bs_u = smem_u32(Bs);

    // per-thread ldmatrix offsets (bytes)
    const uint32_t a_off = 2 * ((wr + (lane & 15)) * ASTR + (lane >> 4) * 8);
    const uint32_t b_off = 2 * (((lane & 7) + (lane & 8)) * BSTR + wc + (lane >> 4) * 8);

    float acc[4][4][4];
#pragma unroll
    for (int i = 0; i < 4; i++)
#pragma unroll
        for (int j = 0; j < 4; j++)
#pragma unroll
            for (int f = 0; f < 4; f++) acc[i][j][f] = 0.f;

    const int KT = K >> 5;   // BK=32

    // tile loader
    auto load_tile = [&](int stage, int k0) {
#pragma unroll
        for (int l = 0; l < 2; l++) {
            int idx = tid + l * 256;
            int m  = idx >> 2, kc = idx & 3;
            cp16(as_u + 2 * (stage * ASZ + m * ASTR + kc * 8),
                 A + (size_t)(brow + m) * K + k0 + kc * 8);
            int kb = idx >> 4, nc = idx & 15;
            cp16(bs_u + 2 * (stage * BSZ + kb * BSTR + nc * 8),
                 B + (size_t)(k0 + kb) * N + bcol + nc * 8);
        }
    };

    load_tile(0, 0);
    CP_COMMIT();

    for (int t = 0; t < KT; t++) {
        const int cur = t & 1;
        if (t + 1 < KT) {
            load_tile(cur ^ 1, (t + 1) * 32);
            CP_COMMIT();
            CP_WAIT(1);
        } else {
            CP_WAIT(0);
        }
        __syncthreads();

        const uint32_t as_s = as_u + 2 * cur * ASZ;
        const uint32_t bs_s = bs_u + 2 * cur * BSZ;
#pragma unroll
        for (int ks = 0; ks < 32; ks += 16) {
            uint32_t af[4][4], bf[4][2];
#pragma unroll
            for (int i = 0; i < 4; i++)
                LDSM_X4(af[i][0], af[i][1], af[i][2], af[i][3],
                        as_s + a_off + 2 * (i * 16 * ASTR + ks));
#pragma unroll
            for (int jp = 0; jp < 2; jp++)
                LDSM_X4_T(bf[2*jp][0], bf[2*jp][1], bf[2*jp+1][0], bf[2*jp+1][1],
                          bs_s + b_off + 2 * (ks * BSTR + jp * 16));
#pragma unroll
            for (int i = 0; i < 4; i++)
#pragma unroll
                for (int j = 0; j < 4; j++)
                    mma_f16(acc[i][j][0], acc[i][j][1], acc[i][j][2], acc[i][j][3],
                            af[i][0], af[i][1], af[i][2], af[i][3],
                            bf[j][0], bf[j][1]);
        }
        __syncthreads();
    }

    // Epilogue
#pragma unroll
    for (int i = 0; i < 4; i++) {
#pragma unroll
        for (int j = 0; j < 4; j++) {
            int row = brow + wr + i * 16 + g;
            int col = bcol + wc + j * 8 + 2 * tig;
            float b0 = bias[col], b1 = bias[col + 1];
            if (WRITE_HALF) {
                __half* Ch = (__half*)Cout;
                *(uint32_t*)&Ch[(size_t)row * N + col] =
                    pack_h2(acc[i][j][0] + b0, acc[i][j][1] + b1);
                *(uint32_t*)&Ch[(size_t)(row + 8) * N + col] =
                    pack_h2(acc[i][j][2] + b0, acc[i][j][3] + b1);
            } else {
                float* Cf = (float*)Cout;
                *(float2*)&Cf[(size_t)row * N + col] =
                    make_float2(acc[i][j][0] + b0, acc[i][j][1] + b1);
                *(float2*)&Cf[(size_t)(row + 8) * N + col] =
                    make_float2(acc[i][j][2] + b0, acc[i][j][3] + b1);
            }
        }
    }
}

// ---------------------------------------------------------------------------
// Causal flash attention, fp16 HMMA + ldmatrix, P kept in registers.
// Grid (T/64, H, B), 128 threads (4 warps). BQ=64 (16 rows/warp), BKV=64.
// ---------------------------------------------------------------------------
#define QVSTR 72    // halves per row (64 + 8 pad)

__global__ __launch_bounds__(128) void attn_h_kernel(
    const __half* __restrict__ qkv, __half* __restrict__ y)
{
    __shared__ __align__(16) __half Qs[64 * QVSTR];
    __shared__ __align__(16) __half Ks[64 * QVSTR];
    __shared__ __align__(16) __half Vs[64 * QVSTR];

    const int qb = blockIdx.x;
    const int h  = blockIdx.y;
    const int b  = blockIdx.z;
    const int tid  = threadIdx.x;
    const int w    = tid >> 5;
    const int lane = tid & 31;
    const int g    = lane >> 2;
    const int tig  = lane & 3;

    const uint32_t qs_u = smem_u32(Qs);
    const uint32_t ks_u = smem_u32(Ks);
    const uint32_t vs_u = smem_u32(Vs);

    // fragment offsets (bytes)
    const uint32_t qa_off = 2 * ((w * 16 + (lane & 15)) * QVSTR + (lane >> 4) * 8);
    const uint32_t kb_off = 2 * (((lane & 7) + ((lane >> 4) ? 8 : 0)) * QVSTR + ((lane & 8) ? 8 : 0));
    const uint32_t vb_off = 2 * (((lane & 7) + (lane & 8)) * QVSTR + ((lane >> 4) ? 8 : 0));

    const __half* base = qkv + (size_t)(b * SEQ) * QKVN + h * HDIM;
    const int q0 = qb * 64;

    // Load Q tile (scaled by 1/8 = 1/sqrt(64); exact in fp16)
    const __half2 sc = __floats2half2_rn(0.125f, 0.125f);
#pragma unroll
    for (int l = 0; l < 4; l++) {
        int idx = tid + l * 128;
        int r = idx >> 3, c8 = (idx & 7) * 8;
        uint4 v = *(const uint4*)&base[(size_t)(q0 + r) * QKVN + c8];
        __half2* hv = (__half2*)&v;
        hv[0] = __hmul2(hv[0], sc); hv[1] = __hmul2(hv[1], sc);
        hv[2] = __hmul2(hv[2], sc); hv[3] = __hmul2(hv[3], sc);
        *(uint4*)&Qs[r * QVSTR + c8] = v;
    }

    float o[8][4];
#pragma unroll
    for (int j = 0; j < 8; j++)
#pragma unroll
        for (int f = 0; f < 4; f++) o[j][f] = 0.f;
    float m0 = -1e30f, m1 = -1e30f, l0 = 0.f, l1 = 0.f;

    for (int kt = 0; kt <= qb; kt++) {
        __syncthreads();
#pragma unroll
        for (int l = 0; l < 4; l++) {
            int idx = tid + l * 128;
            int r = idx >> 3, c8 = (idx & 7) * 8;
            size_t ro = (size_t)(kt * 64 + r) * QKVN + c8;
            *(uint4*)&Ks[r * QVSTR + c8] = *(const uint4*)&base[CDIM + ro];
            *(uint4*)&Vs[r * QVSTR + c8] = *(const uint4*)&base[2 * CDIM + ro];
        }
        __syncthreads();

        // S = Q K^T  (warp rows 16, cols 64)
        float s[8][4];
#pragma unroll
        for (int j = 0; j < 8; j++)
#pragma unroll
            for (int f = 0; f < 4; f++) s[j][f] = 0.f;
#pragma unroll
        for (int ks = 0; ks < 64; ks += 16) {
            uint32_t a0, a1, a2, a3;
            LDSM_X4(a0, a1, a2, a3, qs_u + qa_off + 2 * ks);
#pragma unroll
            for (int jp = 0; jp < 4; jp++) {
                uint32_t b0, b1, b2, b3;
                LDSM_X4(b0, b1, b2, b3, ks_u + kb_off + 2 * (jp * 16 * QVSTR + ks));
                mma_f16(s[2*jp][0], s[2*jp][1], s[2*jp][2], s[2*jp][3],
                        a0, a1, a2, a3, b0, b1);
                mma_f16(s[2*jp+1][0], s[2*jp+1][1], s[2*jp+1][2], s[2*jp+1][3],
                        a0, a1, a2, a3, b2, b3);
            }
        }

        // Causal mask on the diagonal tile
        if (kt == qb) {
            const int rl0 = w * 16 + g, rl1 = rl0 + 8;
#pragma unroll
            for (int j = 0; j < 8; j++) {
                int c = j * 8 + 2 * tig;
                if (c     > rl0) s[j][0] = -1e30f;
                if (c + 1 > rl0) s[j][1] = -1e30f;
                if (c     > rl1) s[j][2] = -1e30f;
                if (c + 1 > rl1) s[j][3] = -1e30f;
            }
        }

        // Online softmax (rows g, g+8); reduce across 4 lanes sharing g
        float rm0 = -1e30f, rm1 = -1e30f;
#pragma unroll
        for (int j = 0; j < 8; j++) {
            rm0 = fmaxf(rm0, fmaxf(s[j][0], s[j][1]));
            rm1 = fmaxf(rm1, fmaxf(s[j][2], s[j][3]));
        }
#pragma unroll
        for (int off = 1; off < 4; off <<= 1) {
            rm0 = fmaxf(rm0, __shfl_xor_sync(0xffffffffu, rm0, off));
            rm1 = fmaxf(rm1, __shfl_xor_sync(0xffffffffu, rm1, off));
        }
        float mn0 = fmaxf(m0, rm0), mn1 = fmaxf(m1, rm1);
        float al0 = __expf(m0 - mn0), al1 = __expf(m1 - mn1);
        float ls0 = 0.f, ls1 = 0.f;
#pragma unroll
        for (int j = 0; j < 8; j++) {
            s[j][0] = __expf(s[j][0] - mn0);
            s[j][1] = __expf(s[j][1] - mn0);
            s[j][2] = __expf(s[j][2] - mn1);
            s[j][3] = __expf(s[j][3] - mn1);
            ls0 += s[j][0] + s[j][1];
            ls1 += s[j][2] + s[j][3];
        }
#pragma unroll
        for (int off = 1; off < 4; off <<= 1) {
            ls0 += __shfl_xor_sync(0xffffffffu, ls0, off);
            ls1 += __shfl_xor_sync(0xffffffffu, ls1, off);
        }
        l0 = l0 * al0 + ls0;
        l1 = l1 * al1 + ls1;
        m0 = mn0; m1 = mn1;
#pragma unroll
        for (int j = 0; j < 8; j++) {
            o[j][0] *= al0; o[j][1] *= al0;
            o[j][2] *= al1; o[j][3] *= al1;
        }

        // O += P @ V  (P from registers; kv=64 -> 4 ksteps; d=64 -> 8 ntiles)
#pragma unroll
        for (int ks2 = 0; ks2 < 4; ks2++) {
            uint32_t a0 = pack_h2(s[2*ks2][0],   s[2*ks2][1]);
            uint32_t a1 = pack_h2(s[2*ks2][2],   s[2*ks2][3]);
            uint32_t a2 = pack_h2(s[2*ks2+1][0], s[2*ks2+1][1]);
            uint32_t a3 = pack_h2(s[2*ks2+1][2], s[2*ks2+1][3]);
#pragma unroll
            for (int jp = 0; jp < 4; jp++) {
                uint32_t b0, b1, b2, b3;
                LDSM_X4_T(b0, b1, b2, b3,
                          vs_u + vb_off + 2 * (ks2 * 16 * QVSTR + jp * 16));
                mma_f16(o[2*jp][0], o[2*jp][1], o[2*jp][2], o[2*jp][3],
                        a0, a1, a2, a3, b0, b1);
                mma_f16(o[2*jp+1][0], o[2*jp+1][1], o[2*jp+1][2], o[2*jp+1][3],
                        a0, a1, a2, a3, b2, b3);
            }
        }
    }

    // Normalize & write y (fp16)
    float il0 = 1.0f / l0, il1 = 1.0f / l1;
    size_t r0 = (size_t)(b * SEQ + q0 + w * 16 + g) * CDIM + h * HDIM;
    size_t r1 = r0 + 8 * CDIM;
#pragma unroll
    for (int j = 0; j < 8; j++) {
        int c = j * 8 + 2 * tig;
        *(uint32_t*)&y[r0 + c] = pack_h2(o[j][0] * il0, o[j][1] * il0);
        *(uint32_t*)&y[r1 + c] = pack_h2(o[j][2] * il1, o[j][3] * il1);
    }
}

// ---------------------------------------------------------------------------
extern "C" void kernel_launch(void* const* d_in, const int* in_sizes, int n_in,
                              void* d_out, int out_size)
{
    const float* x      = (const float*)d_in[0];
    const float* W_attn = (const float*)d_in[1];
    const float* b_attn = (const float*)d_in[2];
    const float* W_proj = (const float*)d_in[3];
    const float* b_proj = (const float*)d_in[4];
    float* out = (float*)d_out;

    __half *xh, *wah, *wph, *qkvh, *yh;
    cudaGetSymbolAddress((void**)&xh,   g_xh);
    cudaGetSymbolAddress((void**)&wah,  g_wah);
    cudaGetSymbolAddress((void**)&wph,  g_wph);
    cudaGetSymbolAddress((void**)&qkvh, g_qkvh);
    cudaGetSymbolAddress((void**)&yh,   g_yh);

    // 0) Convert inputs to fp16
    {
        int n4 = (MROWS * CDIM) / 4;
        f2h_kernel<<<(n4 + 255) / 256, 256>>>((const float4*)x, (uint2*)xh, n4);
        n4 = (CDIM * QKVN) / 4;
        f2h_kernel<<<(n4 + 255) / 256, 256>>>((const float4*)W_attn, (uint2*)wah, n4);
        n4 = (CDIM * CDIM) / 4;
        f2h_kernel<<<(n4 + 255) / 256, 256>>>((const float4*)W_proj, (uint2*)wph, n4);
    }
    // 1) QKV projection (fp16 out)
    {
        dim3 grid(QKVN / 128, MROWS / 128);
        hgemm_bias<1><<<grid, 256>>>(xh, wah, b_attn, qkvh, MROWS, QKVN, CDIM);
    }
    // 2) Causal attention (fp16 out)
    {
        dim3 grid(SEQ / 64, NHEAD, BATCH);
        attn_h_kernel<<<grid, 128>>>(qkvh, yh);
    }
    // 3) Output projection (fp32 out)
    {
        dim3 grid(CDIM / 128, MROWS / 128);
        hgemm_bias<0><<<grid, 256>>>(yh, wph, b_proj, out, MROWS, CDIM, CDIM);
    }
}